// round 14
// baseline (speedup 1.0000x reference)
#include <cuda_runtime.h>

// PointNetKnnInterpolator: fused edge-MLP + segment_max, fp32x2 packed FMA.
// Fully software-pipelined: W double-buffered one kk-step ahead (SSA via
// unrolled kk loop), A double-buffered one chunk ahead (loads folded into
// kk=0/1 of the previous chunk). Every LDS result is consumed >=64 pipe-cyc
// after issue -> smem latency hidden even at 2 warps/SMSP.
//
// Block = 32 y's = 256 edges, 256 threads. Thread tile: 8 edges (all edges
// of one y) x 8 feats, accumulators packed f32x2 along features.

#define THREADS 256
#define EDGES 256
#define YPB 32

#define OFF_WA   0
#define OFF_W1A  (68*64)
#define OFF_WS   (132*64)
#define OFF_W0B  (200*64)
#define OFF_W1B  (264*64)
#define OFF_BIAS (328*64)
#define OFF_H    (OFF_BIAS + 256)
#define OFF_B1   (OFF_H + 256*68)
#define SMEM_FLOATS (OFF_B1 + 256*68)
#define SMEM_BYTES (SMEM_FLOATS * 4)   // 224256

typedef unsigned long long u64;

__device__ __forceinline__ u64 dup2(float a) {
    u64 r;
    asm("mov.b64 %0, {%1, %1};" : "=l"(r) : "f"(a));
    return r;
}
__device__ __forceinline__ void fma2(u64& acc, u64 a, u64 b) {
    asm("fma.rn.f32x2 %0, %1, %2, %3;" : "=l"(acc) : "l"(a), "l"(b), "l"(acc));
}
__device__ __forceinline__ u64 add2(u64 a, u64 b) {
    u64 r;
    asm("add.rn.f32x2 %0, %1, %2;" : "=l"(r) : "l"(a), "l"(b));
    return r;
}
__device__ __forceinline__ float2 unpack2(u64 v) {
    float2 f;
    asm("mov.b64 {%0, %1}, %2;" : "=f"(f.x), "=f"(f.y) : "l"(v));
    return f;
}

__device__ __forceinline__ void loadW(const float* __restrict__ wk, u64 (&w)[4]) {
    ulonglong2 w01 = *(const ulonglong2*)(wk);
    ulonglong2 w23 = *(const ulonglong2*)(wk + 32);
    w[0] = w01.x; w[1] = w01.y; w[2] = w23.x; w[3] = w23.y;
}

// Load one K-chunk (4 k-values x 8 rows) of A into registers.
template<bool RELUA>
__device__ __forceinline__ void loadA(const float* __restrict__ arow,
                                      int coff, float (&a)[8][4])
{
#pragma unroll
    for (int r = 0; r < 8; r++) {
        float4 v = *(const float4*)(arow + r * 68 + coff);
        a[r][0] = v.x; a[r][1] = v.y; a[r][2] = v.z; a[r][3] = v.w;
        if (RELUA) {
#pragma unroll
            for (int q = 0; q < 4; q++) a[r][q] = fmaxf(a[r][q], 0.0f);
        }
    }
}

// One chunk: 128 fma2, with W prefetched one kk ahead and (optionally)
// next chunk's A prefetched during kk=0/1. wcur holds W row kk=0 on entry,
// holds W row 0 of the NEXT chunk (loaded from wnext0) on exit.
template<bool RELUA, bool PFA>
__device__ __forceinline__ void chunk_body(const float* __restrict__ arow,
                                           const float* __restrict__ wchunk,
                                           const float* __restrict__ wnext0,
                                           int pf_coff,
                                           const float (&a)[8][4],
                                           float (&apf)[8][4],
                                           u64 (&wcur)[4],
                                           u64 (&acc)[8][4])
{
#pragma unroll
    for (int kk = 0; kk < 4; kk++) {
        u64 wnxt[4];
        loadW((kk < 3) ? (wchunk + (kk + 1) * 64) : wnext0, wnxt);
        if (PFA && kk < 2) {
#pragma unroll
            for (int r4 = 0; r4 < 4; r4++) {
                const int rr = kk * 4 + r4;
                float4 v = *(const float4*)(arow + rr * 68 + pf_coff);
                apf[rr][0] = v.x; apf[rr][1] = v.y;
                apf[rr][2] = v.z; apf[rr][3] = v.w;
                if (RELUA) {
#pragma unroll
                    for (int q = 0; q < 4; q++)
                        apf[rr][q] = fmaxf(apf[rr][q], 0.0f);
                }
            }
        }
#pragma unroll
        for (int r = 0; r < 8; r++) {
            u64 a2 = dup2(a[r][kk]);
            fma2(acc[r][0], a2, wcur[0]);
            fma2(acc[r][1], a2, wcur[1]);
            fma2(acc[r][2], a2, wcur[2]);
            fma2(acc[r][3], a2, wcur[3]);
        }
#pragma unroll
        for (int q = 0; q < 4; q++) wcur[q] = wnxt[q];   // SSA, no real movs
    }
}

// Full GEMM: 16 swizzled chunks (+ optional tail chunk 16 at coff 64).
template<bool RELUA, bool TAIL>
__device__ __forceinline__ void gemm_f32x2(const float* __restrict__ As,
                                           const float* __restrict__ Ws,
                                           u64 (&acc)[8][4],
                                           int rowbase, int key, int tx)
{
    const float* arow = As + rowbase * 68;
    const float* wb = Ws + (tx << 2);
    float a0[8][4], a1[8][4];
    u64 wcur[4];

    loadA<RELUA>(arow, (key << 2), a0);      // chunk 0 (coff = (0^key)<<2)
    loadW(wb, wcur);                          // W row 0 of chunk 0

#pragma unroll 1
    for (int c = 0; c < 16; c += 2) {
        // chunk c: compute with a0, prefetch A(c+1) -> a1
        chunk_body<RELUA, true>(arow, wb + (c << 8), wb + ((c + 1) << 8),
                                (((c + 1) ^ key) << 2), a0, a1, wcur, acc);
        // chunk c+1: compute with a1, prefetch A(c+2 or tail) -> a0
        const bool more = (c + 2 < 16);
        const float* wn2 = more ? (wb + ((c + 2) << 8))
                                : (TAIL ? (wb + (16 << 8)) : wb);
        const int pf2 = more ? (((c + 2) ^ key) << 2) : 64;
        chunk_body<RELUA, true>(arow, wb + ((c + 1) << 8), wn2,
                                pf2, a1, a0, wcur, acc);
    }
    if (TAIL)
        chunk_body<RELUA, false>(arow, wb + (16 << 8), wb, 0, a0, a1, wcur, acc);
}

__device__ __forceinline__ void init_bias(u64 (&acc)[8][4],
                                          const float* __restrict__ bias, int tx)
{
    ulonglong2 b01 = *(const ulonglong2*)(bias + 8 * tx);
    ulonglong2 b23 = *(const ulonglong2*)(bias + 8 * tx + 4);
#pragma unroll
    for (int r = 0; r < 8; r++) {
        acc[r][0] = b01.x; acc[r][1] = b01.y;
        acc[r][2] = b23.x; acc[r][3] = b23.y;
    }
}

__device__ __forceinline__ void store_tile(float* __restrict__ Bf,
                                           const u64 (&acc)[8][4],
                                           int rowbase, int key, int tx)
{
    const int p0 = ((2 * tx) ^ key) << 2;
    const int p1 = ((2 * tx + 1) ^ key) << 2;
#pragma unroll
    for (int r = 0; r < 8; r++) {
        float* rowp = Bf + (rowbase + r) * 68;
        *(ulonglong2*)(rowp + p0) = make_ulonglong2(acc[r][0], acc[r][1]);
        *(ulonglong2*)(rowp + p1) = make_ulonglong2(acc[r][2], acc[r][3]);
    }
}

__global__ void __launch_bounds__(THREADS, 1)
pointnet_knn_kernel(const float* __restrict__ x,
                    const float* __restrict__ pos_x,
                    const float* __restrict__ pos_y,
                    const int*   __restrict__ x_idx,
                    const int*   __restrict__ y_idx,
                    const float* __restrict__ W0a, const float* __restrict__ b0a,
                    const float* __restrict__ W1a, const float* __restrict__ b1a,
                    const float* __restrict__ Wsa,
                    const float* __restrict__ W0b, const float* __restrict__ b0b,
                    const float* __restrict__ W1b, const float* __restrict__ b1b,
                    float* __restrict__ out, int NY, int E)
{
    extern __shared__ float s[];
    const int tid = threadIdx.x;

    // ---- stage weights (swizzled: src chunk g of row k -> pos (g>>1)+8*(g&1)) ----
    auto cpw = [&](float* dst, const float* src, int rows) {
        const int n4 = rows * 16;
        const float4* s4 = (const float4*)src;
        float4* d4 = (float4*)dst;
        for (int i = tid; i < n4; i += THREADS) {
            const int k = i >> 4, g = i & 15;
            d4[(k << 4) + (g >> 1) + ((g & 1) << 3)] = s4[i];
        }
    };
    cpw(s + OFF_WA,  W0a, 67);
    cpw(s + OFF_W1A, W1a, 64);
    cpw(s + OFF_WS,  Wsa, 67);
    cpw(s + OFF_W0B, W0b, 64);
    cpw(s + OFF_W1B, W1b, 64);
    if (tid < 64) {
        s[OFF_WA + 67 * 64 + tid] = 0.0f;   // zero-pad k=67 row
        s[OFF_WS + 67 * 64 + tid] = 0.0f;
        s[OFF_BIAS +       tid] = b0a[tid];
        s[OFF_BIAS +  64 + tid] = b1a[tid];
        s[OFF_BIAS + 128 + tid] = b0b[tid];
        s[OFF_BIAS + 192 + tid] = b1b[tid];
    }

    // ---- gather H (256 edges x 68), chunk-XOR swizzled, 1 thread/edge ----
    {
        const int el = tid;
        const int ge = blockIdx.x * EDGES + el;
        const int keyE = (el >> 3) & 3;
        float* hr = s + OFF_H + el * 68;
        if (ge < E) {
            const int i = x_idx[ge];
            const float4* xr = (const float4*)(x + (size_t)i * 64);
#pragma unroll
            for (int c = 0; c < 16; c++)
                *(float4*)(hr + ((c ^ keyE) << 2)) = xr[c];
            const int j = y_idx[ge];
            hr[64] = pos_x[3 * (size_t)i + 0] - pos_y[3 * (size_t)j + 0];
            hr[65] = pos_x[3 * (size_t)i + 1] - pos_y[3 * (size_t)j + 1];
            hr[66] = pos_x[3 * (size_t)i + 2] - pos_y[3 * (size_t)j + 2];
            hr[67] = 0.0f;
        } else {
            const float4 z = make_float4(0.f, 0.f, 0.f, 0.f);
#pragma unroll
            for (int c = 0; c < 16; c++)
                *(float4*)(hr + ((c ^ keyE) << 2)) = z;
            hr[64] = hr[65] = hr[66] = hr[67] = 0.0f;
        }
    }
    __syncthreads();

    const int ty = tid >> 3;          // 0..31 -> y within block; edges 8*ty..8*ty+7
    const int tx = tid & 7;           // 0..7  -> feats 8*tx..8*tx+7
    const int rowbase = 8 * ty;
    const int key = ty & 3;           // chunk-permutation key, constant per thread
    const float* Hs = s + OFF_H;
    float* B1 = s + OFF_B1;
    u64 acc[8][4];

    // G1: net = relu(H)@W0a + b0a -> B1
    init_bias(acc, s + OFF_BIAS, tx);
    gemm_f32x2<true, true>(Hs, s + OFF_WA, acc, rowbase, key, tx);
    store_tile(B1, acc, rowbase, key, tx);
    __syncthreads();

    // G2: dx = relu(net)@W1a + b1a   (stays in acc)
    init_bias(acc, s + OFF_BIAS + 64, tx);
    gemm_f32x2<true, false>(B1, s + OFF_W1A, acc, rowbase, key, tx);

    // G3: h2 = dx + H@Wsa -> B1  (barrier only right before overwriting B1)
    gemm_f32x2<false, true>(Hs, s + OFF_WS, acc, rowbase, key, tx);
    __syncthreads();                  // all G2 reads of B1 complete
    store_tile(B1, acc, rowbase, key, tx);
    __syncthreads();

    // G4: net2 = relu(h2)@W0b + b0b -> stored into H (dead)
    init_bias(acc, s + OFF_BIAS + 128, tx);
    gemm_f32x2<true, false>(B1, s + OFF_W0B, acc, rowbase, key, tx);
    store_tile(s + OFF_H, acc, rowbase, key, tx);
    __syncthreads();

    // G5: h3 = (h2 + b1b) + relu(net2)@W1b
    {
        ulonglong2 b01 = *(const ulonglong2*)(s + OFF_BIAS + 192 + 8 * tx);
        ulonglong2 b23 = *(const ulonglong2*)(s + OFF_BIAS + 192 + 8 * tx + 4);
        const int p0 = ((2 * tx) ^ key) << 2;
        const int p1 = ((2 * tx + 1) ^ key) << 2;
#pragma unroll
        for (int r = 0; r < 8; r++) {
            const float* rowp = B1 + (rowbase + r) * 68;
            ulonglong2 qa = *(const ulonglong2*)(rowp + p0);
            ulonglong2 qb = *(const ulonglong2*)(rowp + p1);
            acc[r][0] = add2(qa.x, b01.x);
            acc[r][1] = add2(qa.y, b01.y);
            acc[r][2] = add2(qb.x, b23.x);
            acc[r][3] = add2(qb.y, b23.y);
        }
    }
    gemm_f32x2<true, false>(s + OFF_H, s + OFF_W1B, acc, rowbase, key, tx);

    // ---- segment max: this thread's 8 rows ARE the 8 edges of y ----
    float m[8];
#pragma unroll
    for (int p = 0; p < 4; p++) {
        float2 v = unpack2(acc[0][p]);
        float mx = v.x, my = v.y;
#pragma unroll
        for (int r = 1; r < 8; r++) {
            float2 w = unpack2(acc[r][p]);
            mx = fmaxf(mx, w.x);
            my = fmaxf(my, w.y);
        }
        m[2 * p] = mx; m[2 * p + 1] = my;
    }

    const int y = blockIdx.x * YPB + ty;
    if (y < NY) {
        float4* o = (float4*)(out + (size_t)y * 64 + 8 * tx);
        o[0] = make_float4(m[0], m[1], m[2], m[3]);
        o[1] = make_float4(m[4], m[5], m[6], m[7]);
    }
}

extern "C" void kernel_launch(void* const* d_in, const int* in_sizes, int n_in,
                              void* d_out, int out_size)
{
    const float* x     = (const float*)d_in[0];
    const float* pos_x = (const float*)d_in[1];
    const float* pos_y = (const float*)d_in[2];
    const int*   x_idx = (const int*)d_in[3];
    const int*   y_idx = (const int*)d_in[4];
    const float* W0a = (const float*)d_in[5];
    const float* b0a = (const float*)d_in[6];
    const float* W1a = (const float*)d_in[7];
    const float* b1a = (const float*)d_in[8];
    const float* Wsa = (const float*)d_in[9];
    const float* W0b = (const float*)d_in[10];
    const float* b0b = (const float*)d_in[11];
    const float* W1b = (const float*)d_in[12];
    const float* b1b = (const float*)d_in[13];
    float* out = (float*)d_out;

    const int NY = in_sizes[2] / 3;   // pos_y is (NY, 3)
    const int E  = in_sizes[3];       // x_idx is (NY*K,)

    cudaFuncSetAttribute(pointnet_knn_kernel,
                         cudaFuncAttributeMaxDynamicSharedMemorySize, SMEM_BYTES);

    const int blocks = (NY + YPB - 1) / YPB;
    pointnet_knn_kernel<<<blocks, THREADS, SMEM_BYTES>>>(
        x, pos_x, pos_y, x_idx, y_idx,
        W0a, b0a, W1a, b1a, Wsa, W0b, b0b, W1b, b1b,
        out, NY, E);
}

// round 15
// speedup vs baseline: 1.0036x; 1.0036x over previous
#include <cuda_runtime.h>

// PointNetKnnInterpolator: fused edge-MLP + segment_max, fp32x2 packed FMA.
// Fully software-pipelined: W double-buffered one kk-step ahead (SSA via
// unrolled kk loop), A double-buffered one chunk ahead (loads folded into
// kk=0/1 of the previous chunk). Every LDS result is consumed >=64 pipe-cyc
// after issue -> smem latency hidden even at 2 warps/SMSP.
//
// Block = 32 y's = 256 edges, 256 threads. Thread tile: 8 edges (all edges
// of one y) x 8 feats, accumulators packed f32x2 along features.

#define THREADS 256
#define EDGES 256
#define YPB 32

#define OFF_WA   0
#define OFF_W1A  (68*64)
#define OFF_WS   (132*64)
#define OFF_W0B  (200*64)
#define OFF_W1B  (264*64)
#define OFF_BIAS (328*64)
#define OFF_H    (OFF_BIAS + 256)
#define OFF_B1   (OFF_H + 256*68)
#define SMEM_FLOATS (OFF_B1 + 256*68)
#define SMEM_BYTES (SMEM_FLOATS * 4)   // 224256

typedef unsigned long long u64;

__device__ __forceinline__ u64 dup2(float a) {
    u64 r;
    asm("mov.b64 %0, {%1, %1};" : "=l"(r) : "f"(a));
    return r;
}
__device__ __forceinline__ void fma2(u64& acc, u64 a, u64 b) {
    asm("fma.rn.f32x2 %0, %1, %2, %3;" : "=l"(acc) : "l"(a), "l"(b), "l"(acc));
}
__device__ __forceinline__ u64 add2(u64 a, u64 b) {
    u64 r;
    asm("add.rn.f32x2 %0, %1, %2;" : "=l"(r) : "l"(a), "l"(b));
    return r;
}
__device__ __forceinline__ float2 unpack2(u64 v) {
    float2 f;
    asm("mov.b64 {%0, %1}, %2;" : "=f"(f.x), "=f"(f.y) : "l"(v));
    return f;
}

__device__ __forceinline__ void loadW(const float* __restrict__ wk, u64 (&w)[4]) {
    ulonglong2 w01 = *(const ulonglong2*)(wk);
    ulonglong2 w23 = *(const ulonglong2*)(wk + 32);
    w[0] = w01.x; w[1] = w01.y; w[2] = w23.x; w[3] = w23.y;
}

// Load one K-chunk (4 k-values x 8 rows) of A into registers.
template<bool RELUA>
__device__ __forceinline__ void loadA(const float* __restrict__ arow,
                                      int coff, float (&a)[8][4])
{
#pragma unroll
    for (int r = 0; r < 8; r++) {
        float4 v = *(const float4*)(arow + r * 68 + coff);
        a[r][0] = v.x; a[r][1] = v.y; a[r][2] = v.z; a[r][3] = v.w;
        if (RELUA) {
#pragma unroll
            for (int q = 0; q < 4; q++) a[r][q] = fmaxf(a[r][q], 0.0f);
        }
    }
}

// One chunk: 128 fma2, with W prefetched one kk ahead and (optionally)
// next chunk's A prefetched during kk=0/1. wcur holds W row kk=0 on entry,
// holds W row 0 of the NEXT chunk (loaded from wnext0) on exit.
template<bool RELUA, bool PFA>
__device__ __forceinline__ void chunk_body(const float* __restrict__ arow,
                                           const float* __restrict__ wchunk,
                                           const float* __restrict__ wnext0,
                                           int pf_coff,
                                           const float (&a)[8][4],
                                           float (&apf)[8][4],
                                           u64 (&wcur)[4],
                                           u64 (&acc)[8][4])
{
#pragma unroll
    for (int kk = 0; kk < 4; kk++) {
        u64 wnxt[4];
        loadW((kk < 3) ? (wchunk + (kk + 1) * 64) : wnext0, wnxt);
        if (PFA && kk < 2) {
#pragma unroll
            for (int r4 = 0; r4 < 4; r4++) {
                const int rr = kk * 4 + r4;
                float4 v = *(const float4*)(arow + rr * 68 + pf_coff);
                apf[rr][0] = v.x; apf[rr][1] = v.y;
                apf[rr][2] = v.z; apf[rr][3] = v.w;
                if (RELUA) {
#pragma unroll
                    for (int q = 0; q < 4; q++)
                        apf[rr][q] = fmaxf(apf[rr][q], 0.0f);
                }
            }
        }
#pragma unroll
        for (int r = 0; r < 8; r++) {
            u64 a2 = dup2(a[r][kk]);
            fma2(acc[r][0], a2, wcur[0]);
            fma2(acc[r][1], a2, wcur[1]);
            fma2(acc[r][2], a2, wcur[2]);
            fma2(acc[r][3], a2, wcur[3]);
        }
#pragma unroll
        for (int q = 0; q < 4; q++) wcur[q] = wnxt[q];   // SSA, no real movs
    }
}

// Full GEMM: 16 swizzled chunks (+ optional tail chunk 16 at coff 64).
template<bool RELUA, bool TAIL>
__device__ __forceinline__ void gemm_f32x2(const float* __restrict__ As,
                                           const float* __restrict__ Ws,
                                           u64 (&acc)[8][4],
                                           int rowbase, int key, int tx)
{
    const float* arow = As + rowbase * 68;
    const float* wb = Ws + (tx << 2);
    float a0[8][4], a1[8][4];
    u64 wcur[4];

    loadA<RELUA>(arow, (key << 2), a0);      // chunk 0 (coff = (0^key)<<2)
    loadW(wb, wcur);                          // W row 0 of chunk 0

#pragma unroll 1
    for (int c = 0; c < 16; c += 2) {
        // chunk c: compute with a0, prefetch A(c+1) -> a1
        chunk_body<RELUA, true>(arow, wb + (c << 8), wb + ((c + 1) << 8),
                                (((c + 1) ^ key) << 2), a0, a1, wcur, acc);
        // chunk c+1: compute with a1, prefetch A(c+2 or tail) -> a0
        const bool more = (c + 2 < 16);
        const float* wn2 = more ? (wb + ((c + 2) << 8))
                                : (TAIL ? (wb + (16 << 8)) : wb);
        const int pf2 = more ? (((c + 2) ^ key) << 2) : 64;
        chunk_body<RELUA, true>(arow, wb + ((c + 1) << 8), wn2,
                                pf2, a1, a0, wcur, acc);
    }
    if (TAIL)
        chunk_body<RELUA, false>(arow, wb + (16 << 8), wb, 0, a0, a1, wcur, acc);
}

__device__ __forceinline__ void init_bias(u64 (&acc)[8][4],
                                          const float* __restrict__ bias, int tx)
{
    ulonglong2 b01 = *(const ulonglong2*)(bias + 8 * tx);
    ulonglong2 b23 = *(const ulonglong2*)(bias + 8 * tx + 4);
#pragma unroll
    for (int r = 0; r < 8; r++) {
        acc[r][0] = b01.x; acc[r][1] = b01.y;
        acc[r][2] = b23.x; acc[r][3] = b23.y;
    }
}

__device__ __forceinline__ void store_tile(float* __restrict__ Bf,
                                           const u64 (&acc)[8][4],
                                           int rowbase, int key, int tx)
{
    const int p0 = ((2 * tx) ^ key) << 2;
    const int p1 = ((2 * tx + 1) ^ key) << 2;
#pragma unroll
    for (int r = 0; r < 8; r++) {
        float* rowp = Bf + (rowbase + r) * 68;
        *(ulonglong2*)(rowp + p0) = make_ulonglong2(acc[r][0], acc[r][1]);
        *(ulonglong2*)(rowp + p1) = make_ulonglong2(acc[r][2], acc[r][3]);
    }
}

__global__ void __launch_bounds__(THREADS, 1)
pointnet_knn_kernel(const float* __restrict__ x,
                    const float* __restrict__ pos_x,
                    const float* __restrict__ pos_y,
                    const int*   __restrict__ x_idx,
                    const int*   __restrict__ y_idx,
                    const float* __restrict__ W0a, const float* __restrict__ b0a,
                    const float* __restrict__ W1a, const float* __restrict__ b1a,
                    const float* __restrict__ Wsa,
                    const float* __restrict__ W0b, const float* __restrict__ b0b,
                    const float* __restrict__ W1b, const float* __restrict__ b1b,
                    float* __restrict__ out, int NY, int E)
{
    extern __shared__ float s[];
    const int tid = threadIdx.x;

    // ---- stage weights (swizzled: src chunk g of row k -> pos (g>>1)+8*(g&1)) ----
    auto cpw = [&](float* dst, const float* src, int rows) {
        const int n4 = rows * 16;
        const float4* s4 = (const float4*)src;
        float4* d4 = (float4*)dst;
        for (int i = tid; i < n4; i += THREADS) {
            const int k = i >> 4, g = i & 15;
            d4[(k << 4) + (g >> 1) + ((g & 1) << 3)] = s4[i];
        }
    };
    cpw(s + OFF_WA,  W0a, 67);
    cpw(s + OFF_W1A, W1a, 64);
    cpw(s + OFF_WS,  Wsa, 67);
    cpw(s + OFF_W0B, W0b, 64);
    cpw(s + OFF_W1B, W1b, 64);
    if (tid < 64) {
        s[OFF_WA + 67 * 64 + tid] = 0.0f;   // zero-pad k=67 row
        s[OFF_WS + 67 * 64 + tid] = 0.0f;
        s[OFF_BIAS +       tid] = b0a[tid];
        s[OFF_BIAS +  64 + tid] = b1a[tid];
        s[OFF_BIAS + 128 + tid] = b0b[tid];
        s[OFF_BIAS + 192 + tid] = b1b[tid];
    }

    // ---- gather H (256 edges x 68), chunk-XOR swizzled, 1 thread/edge ----
    {
        const int el = tid;
        const int ge = blockIdx.x * EDGES + el;
        const int keyE = (el >> 3) & 3;
        float* hr = s + OFF_H + el * 68;
        if (ge < E) {
            const int i = x_idx[ge];
            const float4* xr = (const float4*)(x + (size_t)i * 64);
#pragma unroll
            for (int c = 0; c < 16; c++)
                *(float4*)(hr + ((c ^ keyE) << 2)) = xr[c];
            const int j = y_idx[ge];
            hr[64] = pos_x[3 * (size_t)i + 0] - pos_y[3 * (size_t)j + 0];
            hr[65] = pos_x[3 * (size_t)i + 1] - pos_y[3 * (size_t)j + 1];
            hr[66] = pos_x[3 * (size_t)i + 2] - pos_y[3 * (size_t)j + 2];
            hr[67] = 0.0f;
        } else {
            const float4 z = make_float4(0.f, 0.f, 0.f, 0.f);
#pragma unroll
            for (int c = 0; c < 16; c++)
                *(float4*)(hr + ((c ^ keyE) << 2)) = z;
            hr[64] = hr[65] = hr[66] = hr[67] = 0.0f;
        }
    }
    __syncthreads();

    const int ty = tid >> 3;          // 0..31 -> y within block; edges 8*ty..8*ty+7
    const int tx = tid & 7;           // 0..7  -> feats 8*tx..8*tx+7
    const int rowbase = 8 * ty;
    const int key = ty & 3;           // chunk-permutation key, constant per thread
    const float* Hs = s + OFF_H;
    float* B1 = s + OFF_B1;
    u64 acc[8][4];

    // G1: net = relu(H)@W0a + b0a -> B1
    init_bias(acc, s + OFF_BIAS, tx);
    gemm_f32x2<true, true>(Hs, s + OFF_WA, acc, rowbase, key, tx);
    store_tile(B1, acc, rowbase, key, tx);
    __syncthreads();

    // G2: dx = relu(net)@W1a + b1a   (stays in acc)
    init_bias(acc, s + OFF_BIAS + 64, tx);
    gemm_f32x2<true, false>(B1, s + OFF_W1A, acc, rowbase, key, tx);

    // G3: h2 = dx + H@Wsa -> B1  (barrier only right before overwriting B1)
    gemm_f32x2<false, true>(Hs, s + OFF_WS, acc, rowbase, key, tx);
    __syncthreads();                  // all G2 reads of B1 complete
    store_tile(B1, acc, rowbase, key, tx);
    __syncthreads();

    // G4: net2 = relu(h2)@W0b + b0b -> stored into H (dead)
    init_bias(acc, s + OFF_BIAS + 128, tx);
    gemm_f32x2<true, false>(B1, s + OFF_W0B, acc, rowbase, key, tx);
    store_tile(s + OFF_H, acc, rowbase, key, tx);
    __syncthreads();

    // G5: h3 = (h2 + b1b) + relu(net2)@W1b
    {
        ulonglong2 b01 = *(const ulonglong2*)(s + OFF_BIAS + 192 + 8 * tx);
        ulonglong2 b23 = *(const ulonglong2*)(s + OFF_BIAS + 192 + 8 * tx + 4);
        const int p0 = ((2 * tx) ^ key) << 2;
        const int p1 = ((2 * tx + 1) ^ key) << 2;
#pragma unroll
        for (int r = 0; r < 8; r++) {
            const float* rowp = B1 + (rowbase + r) * 68;
            ulonglong2 qa = *(const ulonglong2*)(rowp + p0);
            ulonglong2 qb = *(const ulonglong2*)(rowp + p1);
            acc[r][0] = add2(qa.x, b01.x);
            acc[r][1] = add2(qa.y, b01.y);
            acc[r][2] = add2(qb.x, b23.x);
            acc[r][3] = add2(qb.y, b23.y);
        }
    }
    gemm_f32x2<true, false>(s + OFF_H, s + OFF_W1B, acc, rowbase, key, tx);

    // ---- segment max: this thread's 8 rows ARE the 8 edges of y ----
    float m[8];
#pragma unroll
    for (int p = 0; p < 4; p++) {
        float2 v = unpack2(acc[0][p]);
        float mx = v.x, my = v.y;
#pragma unroll
        for (int r = 1; r < 8; r++) {
            float2 w = unpack2(acc[r][p]);
            mx = fmaxf(mx, w.x);
            my = fmaxf(my, w.y);
        }
        m[2 * p] = mx; m[2 * p + 1] = my;
    }

    const int y = blockIdx.x * YPB + ty;
    if (y < NY) {
        float4* o = (float4*)(out + (size_t)y * 64 + 8 * tx);
        o[0] = make_float4(m[0], m[1], m[2], m[3]);
        o[1] = make_float4(m[4], m[5], m[6], m[7]);
    }
}

extern "C" void kernel_launch(void* const* d_in, const int* in_sizes, int n_in,
                              void* d_out, int out_size)
{
    const float* x     = (const float*)d_in[0];
    const float* pos_x = (const float*)d_in[1];
    const float* pos_y = (const float*)d_in[2];
    const int*   x_idx = (const int*)d_in[3];
    const int*   y_idx = (const int*)d_in[4];
    const float* W0a = (const float*)d_in[5];
    const float* b0a = (const float*)d_in[6];
    const float* W1a = (const float*)d_in[7];
    const float* b1a = (const float*)d_in[8];
    const float* Wsa = (const float*)d_in[9];
    const float* W0b = (const float*)d_in[10];
    const float* b0b = (const float*)d_in[11];
    const float* W1b = (const float*)d_in[12];
    const float* b1b = (const float*)d_in[13];
    float* out = (float*)d_out;

    const int NY = in_sizes[2] / 3;   // pos_y is (NY, 3)
    const int E  = in_sizes[3];       // x_idx is (NY*K,)

    cudaFuncSetAttribute(pointnet_knn_kernel,
                         cudaFuncAttributeMaxDynamicSharedMemorySize, SMEM_BYTES);

    const int blocks = (NY + YPB - 1) / YPB;
    pointnet_knn_kernel<<<blocks, THREADS, SMEM_BYTES>>>(
        x, pos_x, pos_y, x_idx, y_idx,
        W0a, b0a, W1a, b1a, Wsa, W0b, b0b, W1b, b1b,
        out, NY, E);
}

// round 16
// speedup vs baseline: 1.0053x; 1.0017x over previous
#include <cuda_runtime.h>

// PointNetKnnInterpolator: fused edge-MLP + segment_max, fp32x2 packed FMA.
// Fully software-pipelined: W double-buffered one kk-step ahead (SSA via
// unrolled kk loop), A double-buffered one chunk ahead (loads folded into
// kk=0/1 of the previous chunk). Every LDS result is consumed >=64 pipe-cyc
// after issue -> smem latency hidden even at 2 warps/SMSP.
//
// Block = 32 y's = 256 edges, 256 threads. Thread tile: 8 edges (all edges
// of one y) x 8 feats, accumulators packed f32x2 along features.

#define THREADS 256
#define EDGES 256
#define YPB 32

#define OFF_WA   0
#define OFF_W1A  (68*64)
#define OFF_WS   (132*64)
#define OFF_W0B  (200*64)
#define OFF_W1B  (264*64)
#define OFF_BIAS (328*64)
#define OFF_H    (OFF_BIAS + 256)
#define OFF_B1   (OFF_H + 256*68)
#define SMEM_FLOATS (OFF_B1 + 256*68)
#define SMEM_BYTES (SMEM_FLOATS * 4)   // 224256

typedef unsigned long long u64;

__device__ __forceinline__ u64 dup2(float a) {
    u64 r;
    asm("mov.b64 %0, {%1, %1};" : "=l"(r) : "f"(a));
    return r;
}
__device__ __forceinline__ void fma2(u64& acc, u64 a, u64 b) {
    asm("fma.rn.f32x2 %0, %1, %2, %3;" : "=l"(acc) : "l"(a), "l"(b), "l"(acc));
}
__device__ __forceinline__ u64 add2(u64 a, u64 b) {
    u64 r;
    asm("add.rn.f32x2 %0, %1, %2;" : "=l"(r) : "l"(a), "l"(b));
    return r;
}
__device__ __forceinline__ float2 unpack2(u64 v) {
    float2 f;
    asm("mov.b64 {%0, %1}, %2;" : "=f"(f.x), "=f"(f.y) : "l"(v));
    return f;
}

__device__ __forceinline__ void loadW(const float* __restrict__ wk, u64 (&w)[4]) {
    ulonglong2 w01 = *(const ulonglong2*)(wk);
    ulonglong2 w23 = *(const ulonglong2*)(wk + 32);
    w[0] = w01.x; w[1] = w01.y; w[2] = w23.x; w[3] = w23.y;
}

// Load one K-chunk (4 k-values x 8 rows) of A into registers.
template<bool RELUA>
__device__ __forceinline__ void loadA(const float* __restrict__ arow,
                                      int coff, float (&a)[8][4])
{
#pragma unroll
    for (int r = 0; r < 8; r++) {
        float4 v = *(const float4*)(arow + r * 68 + coff);
        a[r][0] = v.x; a[r][1] = v.y; a[r][2] = v.z; a[r][3] = v.w;
        if (RELUA) {
#pragma unroll
            for (int q = 0; q < 4; q++) a[r][q] = fmaxf(a[r][q], 0.0f);
        }
    }
}

// One chunk: 128 fma2, with W prefetched one kk ahead and (optionally)
// next chunk's A prefetched during kk=0/1. wcur holds W row kk=0 on entry,
// holds W row 0 of the NEXT chunk (loaded from wnext0) on exit.
template<bool RELUA, bool PFA>
__device__ __forceinline__ void chunk_body(const float* __restrict__ arow,
                                           const float* __restrict__ wchunk,
                                           const float* __restrict__ wnext0,
                                           int pf_coff,
                                           const float (&a)[8][4],
                                           float (&apf)[8][4],
                                           u64 (&wcur)[4],
                                           u64 (&acc)[8][4])
{
#pragma unroll
    for (int kk = 0; kk < 4; kk++) {
        u64 wnxt[4];
        loadW((kk < 3) ? (wchunk + (kk + 1) * 64) : wnext0, wnxt);
        if (PFA && kk < 2) {
#pragma unroll
            for (int r4 = 0; r4 < 4; r4++) {
                const int rr = kk * 4 + r4;
                float4 v = *(const float4*)(arow + rr * 68 + pf_coff);
                apf[rr][0] = v.x; apf[rr][1] = v.y;
                apf[rr][2] = v.z; apf[rr][3] = v.w;
                if (RELUA) {
#pragma unroll
                    for (int q = 0; q < 4; q++)
                        apf[rr][q] = fmaxf(apf[rr][q], 0.0f);
                }
            }
        }
#pragma unroll
        for (int r = 0; r < 8; r++) {
            u64 a2 = dup2(a[r][kk]);
            fma2(acc[r][0], a2, wcur[0]);
            fma2(acc[r][1], a2, wcur[1]);
            fma2(acc[r][2], a2, wcur[2]);
            fma2(acc[r][3], a2, wcur[3]);
        }
#pragma unroll
        for (int q = 0; q < 4; q++) wcur[q] = wnxt[q];   // SSA, no real movs
    }
}

// Full GEMM: 16 swizzled chunks (+ optional tail chunk 16 at coff 64).
template<bool RELUA, bool TAIL>
__device__ __forceinline__ void gemm_f32x2(const float* __restrict__ As,
                                           const float* __restrict__ Ws,
                                           u64 (&acc)[8][4],
                                           int rowbase, int key, int tx)
{
    const float* arow = As + rowbase * 68;
    const float* wb = Ws + (tx << 2);
    float a0[8][4], a1[8][4];
    u64 wcur[4];

    loadA<RELUA>(arow, (key << 2), a0);      // chunk 0 (coff = (0^key)<<2)
    loadW(wb, wcur);                          // W row 0 of chunk 0

#pragma unroll 1
    for (int c = 0; c < 16; c += 2) {
        // chunk c: compute with a0, prefetch A(c+1) -> a1
        chunk_body<RELUA, true>(arow, wb + (c << 8), wb + ((c + 1) << 8),
                                (((c + 1) ^ key) << 2), a0, a1, wcur, acc);
        // chunk c+1: compute with a1, prefetch A(c+2 or tail) -> a0
        const bool more = (c + 2 < 16);
        const float* wn2 = more ? (wb + ((c + 2) << 8))
                                : (TAIL ? (wb + (16 << 8)) : wb);
        const int pf2 = more ? (((c + 2) ^ key) << 2) : 64;
        chunk_body<RELUA, true>(arow, wb + ((c + 1) << 8), wn2,
                                pf2, a1, a0, wcur, acc);
    }
    if (TAIL)
        chunk_body<RELUA, false>(arow, wb + (16 << 8), wb, 0, a0, a1, wcur, acc);
}

__device__ __forceinline__ void init_bias(u64 (&acc)[8][4],
                                          const float* __restrict__ bias, int tx)
{
    ulonglong2 b01 = *(const ulonglong2*)(bias + 8 * tx);
    ulonglong2 b23 = *(const ulonglong2*)(bias + 8 * tx + 4);
#pragma unroll
    for (int r = 0; r < 8; r++) {
        acc[r][0] = b01.x; acc[r][1] = b01.y;
        acc[r][2] = b23.x; acc[r][3] = b23.y;
    }
}

__device__ __forceinline__ void store_tile(float* __restrict__ Bf,
                                           const u64 (&acc)[8][4],
                                           int rowbase, int key, int tx)
{
    const int p0 = ((2 * tx) ^ key) << 2;
    const int p1 = ((2 * tx + 1) ^ key) << 2;
#pragma unroll
    for (int r = 0; r < 8; r++) {
        float* rowp = Bf + (rowbase + r) * 68;
        *(ulonglong2*)(rowp + p0) = make_ulonglong2(acc[r][0], acc[r][1]);
        *(ulonglong2*)(rowp + p1) = make_ulonglong2(acc[r][2], acc[r][3]);
    }
}

__global__ void __launch_bounds__(THREADS, 1)
pointnet_knn_kernel(const float* __restrict__ x,
                    const float* __restrict__ pos_x,
                    const float* __restrict__ pos_y,
                    const int*   __restrict__ x_idx,
                    const int*   __restrict__ y_idx,
                    const float* __restrict__ W0a, const float* __restrict__ b0a,
                    const float* __restrict__ W1a, const float* __restrict__ b1a,
                    const float* __restrict__ Wsa,
                    const float* __restrict__ W0b, const float* __restrict__ b0b,
                    const float* __restrict__ W1b, const float* __restrict__ b1b,
                    float* __restrict__ out, int NY, int E)
{
    extern __shared__ float s[];
    const int tid = threadIdx.x;

    // ---- stage weights (swizzled: src chunk g of row k -> pos (g>>1)+8*(g&1)) ----
    auto cpw = [&](float* dst, const float* src, int rows) {
        const int n4 = rows * 16;
        const float4* s4 = (const float4*)src;
        float4* d4 = (float4*)dst;
        for (int i = tid; i < n4; i += THREADS) {
            const int k = i >> 4, g = i & 15;
            d4[(k << 4) + (g >> 1) + ((g & 1) << 3)] = s4[i];
        }
    };
    cpw(s + OFF_WA,  W0a, 67);
    cpw(s + OFF_W1A, W1a, 64);
    cpw(s + OFF_WS,  Wsa, 67);
    cpw(s + OFF_W0B, W0b, 64);
    cpw(s + OFF_W1B, W1b, 64);
    if (tid < 64) {
        s[OFF_WA + 67 * 64 + tid] = 0.0f;   // zero-pad k=67 row
        s[OFF_WS + 67 * 64 + tid] = 0.0f;
        s[OFF_BIAS +       tid] = b0a[tid];
        s[OFF_BIAS +  64 + tid] = b1a[tid];
        s[OFF_BIAS + 128 + tid] = b0b[tid];
        s[OFF_BIAS + 192 + tid] = b1b[tid];
    }

    // ---- gather H (256 edges x 68), chunk-XOR swizzled, 1 thread/edge ----
    {
        const int el = tid;
        const int ge = blockIdx.x * EDGES + el;
        const int keyE = (el >> 3) & 3;
        float* hr = s + OFF_H + el * 68;
        if (ge < E) {
            const int i = x_idx[ge];
            const float4* xr = (const float4*)(x + (size_t)i * 64);
#pragma unroll
            for (int c = 0; c < 16; c++)
                *(float4*)(hr + ((c ^ keyE) << 2)) = xr[c];
            const int j = y_idx[ge];
            hr[64] = pos_x[3 * (size_t)i + 0] - pos_y[3 * (size_t)j + 0];
            hr[65] = pos_x[3 * (size_t)i + 1] - pos_y[3 * (size_t)j + 1];
            hr[66] = pos_x[3 * (size_t)i + 2] - pos_y[3 * (size_t)j + 2];
            hr[67] = 0.0f;
        } else {
            const float4 z = make_float4(0.f, 0.f, 0.f, 0.f);
#pragma unroll
            for (int c = 0; c < 16; c++)
                *(float4*)(hr + ((c ^ keyE) << 2)) = z;
            hr[64] = hr[65] = hr[66] = hr[67] = 0.0f;
        }
    }
    __syncthreads();

    const int ty = tid >> 3;          // 0..31 -> y within block; edges 8*ty..8*ty+7
    const int tx = tid & 7;           // 0..7  -> feats 8*tx..8*tx+7
    const int rowbase = 8 * ty;
    const int key = ty & 3;           // chunk-permutation key, constant per thread
    const float* Hs = s + OFF_H;
    float* B1 = s + OFF_B1;
    u64 acc[8][4];

    // G1: net = relu(H)@W0a + b0a -> B1
    init_bias(acc, s + OFF_BIAS, tx);
    gemm_f32x2<true, true>(Hs, s + OFF_WA, acc, rowbase, key, tx);
    store_tile(B1, acc, rowbase, key, tx);
    __syncthreads();

    // G2: dx = relu(net)@W1a + b1a   (stays in acc)
    init_bias(acc, s + OFF_BIAS + 64, tx);
    gemm_f32x2<true, false>(B1, s + OFF_W1A, acc, rowbase, key, tx);

    // G3: h2 = dx + H@Wsa -> B1  (barrier only right before overwriting B1)
    gemm_f32x2<false, true>(Hs, s + OFF_WS, acc, rowbase, key, tx);
    __syncthreads();                  // all G2 reads of B1 complete
    store_tile(B1, acc, rowbase, key, tx);
    __syncthreads();

    // G4: net2 = relu(h2)@W0b + b0b -> stored into H (dead)
    init_bias(acc, s + OFF_BIAS + 128, tx);
    gemm_f32x2<true, false>(B1, s + OFF_W0B, acc, rowbase, key, tx);
    store_tile(s + OFF_H, acc, rowbase, key, tx);
    __syncthreads();

    // G5: h3 = (h2 + b1b) + relu(net2)@W1b
    {
        ulonglong2 b01 = *(const ulonglong2*)(s + OFF_BIAS + 192 + 8 * tx);
        ulonglong2 b23 = *(const ulonglong2*)(s + OFF_BIAS + 192 + 8 * tx + 4);
        const int p0 = ((2 * tx) ^ key) << 2;
        const int p1 = ((2 * tx + 1) ^ key) << 2;
#pragma unroll
        for (int r = 0; r < 8; r++) {
            const float* rowp = B1 + (rowbase + r) * 68;
            ulonglong2 qa = *(const ulonglong2*)(rowp + p0);
            ulonglong2 qb = *(const ulonglong2*)(rowp + p1);
            acc[r][0] = add2(qa.x, b01.x);
            acc[r][1] = add2(qa.y, b01.y);
            acc[r][2] = add2(qb.x, b23.x);
            acc[r][3] = add2(qb.y, b23.y);
        }
    }
    gemm_f32x2<true, false>(s + OFF_H, s + OFF_W1B, acc, rowbase, key, tx);

    // ---- segment max: this thread's 8 rows ARE the 8 edges of y ----
    float m[8];
#pragma unroll
    for (int p = 0; p < 4; p++) {
        float2 v = unpack2(acc[0][p]);
        float mx = v.x, my = v.y;
#pragma unroll
        for (int r = 1; r < 8; r++) {
            float2 w = unpack2(acc[r][p]);
            mx = fmaxf(mx, w.x);
            my = fmaxf(my, w.y);
        }
        m[2 * p] = mx; m[2 * p + 1] = my;
    }

    const int y = blockIdx.x * YPB + ty;
    if (y < NY) {
        float4* o = (float4*)(out + (size_t)y * 64 + 8 * tx);
        o[0] = make_float4(m[0], m[1], m[2], m[3]);
        o[1] = make_float4(m[4], m[5], m[6], m[7]);
    }
}

extern "C" void kernel_launch(void* const* d_in, const int* in_sizes, int n_in,
                              void* d_out, int out_size)
{
    const float* x     = (const float*)d_in[0];
    const float* pos_x = (const float*)d_in[1];
    const float* pos_y = (const float*)d_in[2];
    const int*   x_idx = (const int*)d_in[3];
    const int*   y_idx = (const int*)d_in[4];
    const float* W0a = (const float*)d_in[5];
    const float* b0a = (const float*)d_in[6];
    const float* W1a = (const float*)d_in[7];
    const float* b1a = (const float*)d_in[8];
    const float* Wsa = (const float*)d_in[9];
    const float* W0b = (const float*)d_in[10];
    const float* b0b = (const float*)d_in[11];
    const float* W1b = (const float*)d_in[12];
    const float* b1b = (const float*)d_in[13];
    float* out = (float*)d_out;

    const int NY = in_sizes[2] / 3;   // pos_y is (NY, 3)
    const int E  = in_sizes[3];       // x_idx is (NY*K,)

    cudaFuncSetAttribute(pointnet_knn_kernel,
                         cudaFuncAttributeMaxDynamicSharedMemorySize, SMEM_BYTES);

    const int blocks = (NY + YPB - 1) / YPB;
    pointnet_knn_kernel<<<blocks, THREADS, SMEM_BYTES>>>(
        x, pos_x, pos_y, x_idx, y_idx,
        W0a, b0a, W1a, b1a, Wsa, W0b, b0b, W1b, b1b,
        out, NY, E);
}

// round 17
// speedup vs baseline: 1.4351x; 1.4275x over previous
#include <cuda_runtime.h>

// PointNetKnnInterpolator, two-phase:
//  K1: per-x-point precompute  xa = relu(x)@W0a[:64],  xs = x@Wsa[:64]
//  K2: per-edge MLP with G1/G3 reduced to K=3 (diff) + gathered xa/xs row,
//      then K=64 GEMMs G2/G4/G5, fused segment_max.
// fp32x2 packed FMA, 8-edge x 8-feat thread tile, chunk-XOR smem swizzle.

#define THREADS 256
#define EDGES 256
#define YPB 32

typedef unsigned long long u64;

#define NX_CAP 20480
__device__ float g_xa[NX_CAP * 64];
__device__ float g_xs[NX_CAP * 64];

__device__ __forceinline__ u64 dup2(float a) {
    u64 r;
    asm("mov.b64 %0, {%1, %1};" : "=l"(r) : "f"(a));
    return r;
}
__device__ __forceinline__ void fma2(u64& acc, u64 a, u64 b) {
    asm("fma.rn.f32x2 %0, %1, %2, %3;" : "=l"(acc) : "l"(a), "l"(b), "l"(acc));
}
__device__ __forceinline__ u64 add2(u64 a, u64 b) {
    u64 r;
    asm("add.rn.f32x2 %0, %1, %2;" : "=l"(r) : "l"(a), "l"(b));
    return r;
}
__device__ __forceinline__ float2 unpack2(u64 v) {
    float2 f;
    asm("mov.b64 {%0, %1}, %2;" : "=f"(f.x), "=f"(f.y) : "l"(v));
    return f;
}

// K=64 GEMM, 16 chunk-XOR-swizzled chunks, A/B row stride 64.
// acc[r][q] packs feats (8tx+2q, 8tx+2q+1).
template<bool RELUA>
__device__ __forceinline__ void gemm64(const float* __restrict__ As,
                                       const float* __restrict__ Ws,
                                       u64 (&acc)[8][4],
                                       int rowbase, int key, int tx)
{
    const float* arow = As + rowbase * 64;
    const float* wb = Ws + (tx << 2);
#pragma unroll 1
    for (int c = 0; c < 16; c++) {
        float a[8][4];
        const int coff = ((c ^ key) << 2);
#pragma unroll
        for (int r = 0; r < 8; r++) {
            float4 v = *(const float4*)(arow + r * 64 + coff);
            a[r][0] = v.x; a[r][1] = v.y; a[r][2] = v.z; a[r][3] = v.w;
            if (RELUA) {
#pragma unroll
                for (int q = 0; q < 4; q++) a[r][q] = fmaxf(a[r][q], 0.0f);
            }
        }
        const float* wk = wb + (c << 8);   // c*4 rows * 64
#pragma unroll
        for (int kk = 0; kk < 4; kk++) {
            ulonglong2 w01 = *(const ulonglong2*)(wk + kk * 64);
            ulonglong2 w23 = *(const ulonglong2*)(wk + kk * 64 + 32);
            u64 W0 = w01.x, W1 = w01.y, W2 = w23.x, W3 = w23.y;
#pragma unroll
            for (int r = 0; r < 8; r++) {
                u64 a2 = dup2(a[r][kk]);
                fma2(acc[r][0], a2, W0);
                fma2(acc[r][1], a2, W1);
                fma2(acc[r][2], a2, W2);
                fma2(acc[r][3], a2, W3);
            }
        }
    }
}

__device__ __forceinline__ void init_bias(u64 (&acc)[8][4],
                                          const float* __restrict__ bias, int tx)
{
    ulonglong2 b01 = *(const ulonglong2*)(bias + 8 * tx);
    ulonglong2 b23 = *(const ulonglong2*)(bias + 8 * tx + 4);
#pragma unroll
    for (int r = 0; r < 8; r++) {
        acc[r][0] = b01.x; acc[r][1] = b01.y;
        acc[r][2] = b23.x; acc[r][3] = b23.y;
    }
}

__device__ __forceinline__ void store_tile(float* __restrict__ Bf,
                                           const u64 (&acc)[8][4],
                                           int rowbase, int key, int tx)
{
    const int p0 = ((2 * tx) ^ key) << 2;
    const int p1 = ((2 * tx + 1) ^ key) << 2;
#pragma unroll
    for (int r = 0; r < 8; r++) {
        float* rowp = Bf + (rowbase + r) * 64;
        *(ulonglong2*)(rowp + p0) = make_ulonglong2(acc[r][0], acc[r][1]);
        *(ulonglong2*)(rowp + p1) = make_ulonglong2(acc[r][2], acc[r][3]);
    }
}

// Swizzled weight staging: src float4 chunk g of row k -> pos (g>>1)+8*(g&1).
__device__ __forceinline__ void stageW(float* dst, const float* src, int tid)
{
    const float4* s4 = (const float4*)src;
    float4* d4 = (float4*)dst;
    for (int i = tid; i < 64 * 16; i += THREADS) {
        const int k = i >> 4, g = i & 15;
        d4[(k << 4) + (g >> 1) + ((g & 1) << 3)] = s4[i];
    }
}

// ============================ Kernel 1: precompute ============================
// xa[i] = relu(x[i]) @ W0a[:64],  xs[i] = x[i] @ Wsa[:64]
#define K1_WA 0
#define K1_WS 4096
#define K1_X  8192
#define K1_FLOATS (K1_X + 256*64)
#define K1_BYTES (K1_FLOATS * 4)   // 98304

__global__ void __launch_bounds__(THREADS, 1)
precompute_kernel(const float* __restrict__ x,
                  const float* __restrict__ W0a,
                  const float* __restrict__ Wsa, int NX)
{
    extern __shared__ float s[];
    const int tid = threadIdx.x;

    stageW(s + K1_WA, W0a, tid);
    stageW(s + K1_WS, Wsa, tid);

    // stage x tile (256 rows x 64), chunk-XOR swizzled
    {
        const int el = tid;
        const int row = blockIdx.x * 256 + el;
        const int keyE = (el >> 3) & 3;
        float* hr = s + K1_X + el * 64;
        if (row < NX) {
            const float4* xr = (const float4*)(x + (size_t)row * 64);
#pragma unroll
            for (int c = 0; c < 16; c++)
                *(float4*)(hr + ((c ^ keyE) << 2)) = xr[c];
        } else {
            const float4 z = make_float4(0.f, 0.f, 0.f, 0.f);
#pragma unroll
            for (int c = 0; c < 16; c++)
                *(float4*)(hr + ((c ^ keyE) << 2)) = z;
        }
    }
    __syncthreads();

    const int ty = tid >> 3, tx = tid & 7;
    const int rowbase = 8 * ty;
    const int key = ty & 3;
    u64 acc[8][4];

    auto store_g = [&](float* g) {
#pragma unroll
        for (int r = 0; r < 8; r++) {
            const int rowg = blockIdx.x * 256 + rowbase + r;
            if (rowg < NX) {
                float2 p0 = unpack2(acc[r][0]), p1 = unpack2(acc[r][1]);
                float2 p2 = unpack2(acc[r][2]), p3 = unpack2(acc[r][3]);
                float4* o = (float4*)(g + (size_t)rowg * 64 + 8 * tx);
                o[0] = make_float4(p0.x, p0.y, p1.x, p1.y);
                o[1] = make_float4(p2.x, p2.y, p3.x, p3.y);
            }
        }
    };

#pragma unroll
    for (int r = 0; r < 8; r++)
#pragma unroll
        for (int q = 0; q < 4; q++) acc[r][q] = 0ull;
    gemm64<true>(s + K1_X, s + K1_WA, acc, rowbase, key, tx);   // relu(x)@W0a
    store_g(g_xa);

#pragma unroll
    for (int r = 0; r < 8; r++)
#pragma unroll
        for (int q = 0; q < 4; q++) acc[r][q] = 0ull;
    gemm64<false>(s + K1_X, s + K1_WS, acc, rowbase, key, tx);  // x@Wsa
    store_g(g_xs);
}

// ============================ Kernel 2: edge MLP ==============================
#define OFF_W1A  0
#define OFF_W0B  4096
#define OFF_W1B  8192
#define OFF_TAIL 12288   // W0a rows 64..66 (192), then Wsa rows 64..66 (192)
#define OFF_BIAS 12672   // b0a,b1a,b0b,b1b
#define OFF_DIFF 12928   // 256 x 4
#define OFF_IDX  13952   // 256 ints
#define OFF_B1   14208   // 256 x 64
#define OFF_B2   (OFF_B1 + 256*64)
#define K2_FLOATS (OFF_B2 + 256*64)
#define K2_BYTES (K2_FLOATS * 4)   // ~188 KB

__global__ void __launch_bounds__(THREADS, 1)
edge_mlp_kernel(const float* __restrict__ pos_x,
                const float* __restrict__ pos_y,
                const int*   __restrict__ x_idx,
                const int*   __restrict__ y_idx,
                const float* __restrict__ W0a, const float* __restrict__ b0a,
                const float* __restrict__ W1a, const float* __restrict__ b1a,
                const float* __restrict__ Wsa,
                const float* __restrict__ W0b, const float* __restrict__ b0b,
                const float* __restrict__ W1b, const float* __restrict__ b1b,
                float* __restrict__ out, int NY, int E)
{
    extern __shared__ float s[];
    const int tid = threadIdx.x;
    int* sidx = (int*)(s + OFF_IDX);

    stageW(s + OFF_W1A, W1a, tid);
    stageW(s + OFF_W0B, W0b, tid);
    stageW(s + OFF_W1B, W1b, tid);
    if (tid < 192) {
        s[OFF_TAIL + tid]       = W0a[64 * 64 + tid];   // rows 64..66
        s[OFF_TAIL + 192 + tid] = Wsa[64 * 64 + tid];
    }
    if (tid < 64) {
        s[OFF_BIAS +       tid] = b0a[tid];
        s[OFF_BIAS +  64 + tid] = b1a[tid];
        s[OFF_BIAS + 128 + tid] = b0b[tid];
        s[OFF_BIAS + 192 + tid] = b1b[tid];
    }

    // ---- gather: indices + diff only ----
    {
        const int el = tid;
        const int ge = blockIdx.x * EDGES + el;
        float* dr = s + OFF_DIFF + el * 4;
        if (ge < E) {
            const int i = x_idx[ge];
            const int j = y_idx[ge];
            sidx[el] = i;
            dr[0] = pos_x[3 * (size_t)i + 0] - pos_y[3 * (size_t)j + 0];
            dr[1] = pos_x[3 * (size_t)i + 1] - pos_y[3 * (size_t)j + 1];
            dr[2] = pos_x[3 * (size_t)i + 2] - pos_y[3 * (size_t)j + 2];
            dr[3] = 0.0f;
        } else {
            sidx[el] = 0;
            dr[0] = dr[1] = dr[2] = dr[3] = 0.0f;
        }
    }
    __syncthreads();

    const int ty = tid >> 3, tx = tid & 7;
    const int rowbase = 8 * ty;
    const int key = ty & 3;
    float* B1 = s + OFF_B1;
    float* B2 = s + OFF_B2;
    u64 acc[8][4];

    // ---- G1: net = xa[i] + b0a + relu(diff)@W0a[64:67] -> B1 ----
    {
        u64 tw[3][4];
#pragma unroll
        for (int t = 0; t < 3; t++) {
            ulonglong2 q0 = *(const ulonglong2*)(s + OFF_TAIL + t * 64 + 8 * tx);
            ulonglong2 q1 = *(const ulonglong2*)(s + OFF_TAIL + t * 64 + 8 * tx + 4);
            tw[t][0] = q0.x; tw[t][1] = q0.y; tw[t][2] = q1.x; tw[t][3] = q1.y;
        }
        ulonglong2 b01 = *(const ulonglong2*)(s + OFF_BIAS + 8 * tx);
        ulonglong2 b23 = *(const ulonglong2*)(s + OFF_BIAS + 8 * tx + 4);
#pragma unroll
        for (int r = 0; r < 8; r++) {
            const int el = rowbase + r;
            const int i = sidx[el];
            const ulonglong2* gp =
                (const ulonglong2*)(g_xa + (size_t)i * 64 + 8 * tx);
            ulonglong2 qa = gp[0], qb = gp[1];
            acc[r][0] = add2(qa.x, b01.x);
            acc[r][1] = add2(qa.y, b01.y);
            acc[r][2] = add2(qb.x, b23.x);
            acc[r][3] = add2(qb.y, b23.y);
            const float* dr = s + OFF_DIFF + el * 4;
#pragma unroll
            for (int t = 0; t < 3; t++) {
                u64 dd = dup2(fmaxf(dr[t], 0.0f));      // relu on diff part
#pragma unroll
                for (int q = 0; q < 4; q++) fma2(acc[r][q], dd, tw[t][q]);
            }
        }
    }
    store_tile(B1, acc, rowbase, key, tx);
    __syncthreads();

    // ---- G2: dx = relu(net)@W1a + b1a (stays in acc) ----
    init_bias(acc, s + OFF_BIAS + 64, tx);
    gemm64<true>(B1, s + OFF_W1A, acc, rowbase, key, tx);

    // ---- G3: h2 = dx + xs[i] + diff@Wsa[64:67] -> B2 ----
    {
        u64 tw[3][4];
#pragma unroll
        for (int t = 0; t < 3; t++) {
            ulonglong2 q0 = *(const ulonglong2*)(s + OFF_TAIL + 192 + t * 64 + 8 * tx);
            ulonglong2 q1 = *(const ulonglong2*)(s + OFF_TAIL + 192 + t * 64 + 8 * tx + 4);
            tw[t][0] = q0.x; tw[t][1] = q0.y; tw[t][2] = q1.x; tw[t][3] = q1.y;
        }
#pragma unroll
        for (int r = 0; r < 8; r++) {
            const int el = rowbase + r;
            const int i = sidx[el];
            const ulonglong2* gp =
                (const ulonglong2*)(g_xs + (size_t)i * 64 + 8 * tx);
            ulonglong2 qa = gp[0], qb = gp[1];
            acc[r][0] = add2(acc[r][0], qa.x);
            acc[r][1] = add2(acc[r][1], qa.y);
            acc[r][2] = add2(acc[r][2], qb.x);
            acc[r][3] = add2(acc[r][3], qb.y);
            const float* dr = s + OFF_DIFF + el * 4;
#pragma unroll
            for (int t = 0; t < 3; t++) {
                u64 dd = dup2(dr[t]);                   // no relu here
#pragma unroll
                for (int q = 0; q < 4; q++) fma2(acc[r][q], dd, tw[t][q]);
            }
        }
    }
    store_tile(B2, acc, rowbase, key, tx);
    __syncthreads();   // also fences all G2 reads of B1

    // ---- G4: net2 = relu(h2)@W0b + b0b -> B1 ----
    init_bias(acc, s + OFF_BIAS + 128, tx);
    gemm64<true>(B2, s + OFF_W0B, acc, rowbase, key, tx);
    store_tile(B1, acc, rowbase, key, tx);
    __syncthreads();

    // ---- G5: h3 = (h2 + b1b) + relu(net2)@W1b ----
    {
        ulonglong2 b01 = *(const ulonglong2*)(s + OFF_BIAS + 192 + 8 * tx);
        ulonglong2 b23 = *(const ulonglong2*)(s + OFF_BIAS + 192 + 8 * tx + 4);
        const int p0 = ((2 * tx) ^ key) << 2;
        const int p1 = ((2 * tx + 1) ^ key) << 2;
#pragma unroll
        for (int r = 0; r < 8; r++) {
            const float* rowp = B2 + (rowbase + r) * 64;
            ulonglong2 qa = *(const ulonglong2*)(rowp + p0);
            ulonglong2 qb = *(const ulonglong2*)(rowp + p1);
            acc[r][0] = add2(qa.x, b01.x);
            acc[r][1] = add2(qa.y, b01.y);
            acc[r][2] = add2(qb.x, b23.x);
            acc[r][3] = add2(qb.y, b23.y);
        }
    }
    gemm64<true>(B1, s + OFF_W1B, acc, rowbase, key, tx);

    // ---- segment max: this thread's 8 rows ARE the 8 edges of y ----
    float m[8];
#pragma unroll
    for (int p = 0; p < 4; p++) {
        float2 v = unpack2(acc[0][p]);
        float mx = v.x, my = v.y;
#pragma unroll
        for (int r = 1; r < 8; r++) {
            float2 w = unpack2(acc[r][p]);
            mx = fmaxf(mx, w.x);
            my = fmaxf(my, w.y);
        }
        m[2 * p] = mx; m[2 * p + 1] = my;
    }

    const int y = blockIdx.x * YPB + ty;
    if (y < NY) {
        float4* o = (float4*)(out + (size_t)y * 64 + 8 * tx);
        o[0] = make_float4(m[0], m[1], m[2], m[3]);
        o[1] = make_float4(m[4], m[5], m[6], m[7]);
    }
}

extern "C" void kernel_launch(void* const* d_in, const int* in_sizes, int n_in,
                              void* d_out, int out_size)
{
    const float* x     = (const float*)d_in[0];
    const float* pos_x = (const float*)d_in[1];
    const float* pos_y = (const float*)d_in[2];
    const int*   x_idx = (const int*)d_in[3];
    const int*   y_idx = (const int*)d_in[4];
    const float* W0a = (const float*)d_in[5];
    const float* b0a = (const float*)d_in[6];
    const float* W1a = (const float*)d_in[7];
    const float* b1a = (const float*)d_in[8];
    const float* Wsa = (const float*)d_in[9];
    const float* W0b = (const float*)d_in[10];
    const float* b0b = (const float*)d_in[11];
    const float* W1b = (const float*)d_in[12];
    const float* b1b = (const float*)d_in[13];
    float* out = (float*)d_out;

    const int NX = in_sizes[0] / 64;  // x is (NX, 64)
    const int NY = in_sizes[2] / 3;   // pos_y is (NY, 3)
    const int E  = in_sizes[3];       // x_idx is (NY*K,)

    cudaFuncSetAttribute(precompute_kernel,
                         cudaFuncAttributeMaxDynamicSharedMemorySize, K1_BYTES);
    cudaFuncSetAttribute(edge_mlp_kernel,
                         cudaFuncAttributeMaxDynamicSharedMemorySize, K2_BYTES);

    const int blocks1 = (NX + 255) / 256;
    precompute_kernel<<<blocks1, THREADS, K1_BYTES>>>(x, W0a, Wsa, NX);

    const int blocks2 = (NY + YPB - 1) / YPB;
    edge_mlp_kernel<<<blocks2, THREADS, K2_BYTES>>>(
        pos_x, pos_y, x_idx, y_idx,
        W0a, b0a, W1a, b1a, Wsa, W0b, b0b, W1b, b1b,
        out, NY, E);
}